// round 5
// baseline (speedup 1.0000x reference)
#include <cuda_runtime.h>
#include <cstdint>
#include <cstddef>

// Problem constants (fixed by setup_inputs).
#define B_Q    256
#define N_BANK 50000
#define DIM_S  4096
#define DIM_D  2048
#define KTOP   9

// ---------------- static device scratch (no allocations allowed) -------------
__device__ __align__(128) float g_scores[(size_t)B_Q * N_BANK];   // 51.2 MB, reused per branch
__device__ __align__(128) float g_inv_sem[N_BANK];
__device__ __align__(128) float g_inv_dst[N_BANK];
__device__ __align__(128) float g_partial[B_Q];

// ---------------- packed fp32x2 helpers (sm_103a FFMA2 path) -----------------
__device__ __forceinline__ unsigned long long pk2(float lo, float hi) {
    unsigned long long r;
    asm("mov.b64 %0, {%1, %2};" : "=l"(r) : "f"(lo), "f"(hi));
    return r;
}
__device__ __forceinline__ void ffma2(unsigned long long& c,
                                      unsigned long long a,
                                      unsigned long long b) {
    asm("fma.rn.f32x2 %0, %1, %2, %0;" : "+l"(c) : "l"(a), "l"(b));
}
__device__ __forceinline__ float2 upk2(unsigned long long x) {
    float2 f;
    asm("mov.b64 {%0, %1}, %2;" : "=f"(f.x), "=f"(f.y) : "l"(x));
    return f;
}

// ---------------- 1) bank row inverse norms (both banks, one launch) ---------
__global__ void norm_kernel(const float* __restrict__ sem_bank,
                            const float* __restrict__ dst_bank) {
    int gwarp = (blockIdx.x * blockDim.x + threadIdx.x) >> 5;
    int lane  = threadIdx.x & 31;
    const float* bank;
    float* outp;
    int D, row;
    if (gwarp < N_BANK)          { bank = sem_bank; outp = g_inv_sem; D = DIM_S; row = gwarp; }
    else if (gwarp < 2 * N_BANK) { bank = dst_bank; outp = g_inv_dst; D = DIM_D; row = gwarp - N_BANK; }
    else return;

    const float4* r4 = reinterpret_cast<const float4*>(bank + (size_t)row * D);
    float s = 0.f;
    int nv = D >> 2;
    for (int i = lane; i < nv; i += 32) {
        float4 v = r4[i];
        s += v.x * v.x + v.y * v.y + v.z * v.z + v.w * v.w;
    }
    #pragma unroll
    for (int o = 16; o; o >>= 1) s += __shfl_xor_sync(0xffffffffu, s, o);
    if (lane == 0) outp[row] = rsqrtf(s);
}

// ---------------- 2) fp32 GEMM with fused invnorm epilogue -------------------
// C[m, n] = (sum_k A[m,k] * Bank[n,k]) * inv[n],  M=256, N=50000, K in {4096,2048}
// Tile: 128(M) x 128(N) x 8(K), 256 threads, 8x8 per thread (4+4 column split
// so stores are contiguous float4 across a half-warp).
#define BM  128
#define BN  128
#define BKK 8

__global__ __launch_bounds__(256, 2)
void gemm_score_kernel(const float* __restrict__ A,
                       const float* __restrict__ Bank,
                       int which,     // 0 = semantic, 1 = distorsion
                       int K)
{
    __shared__ float As[BKK][BM];
    __shared__ float Bs[BKK][BN];

    const float* __restrict__ inv = which ? g_inv_dst : g_inv_sem;
    float* __restrict__ C = g_scores;

    const int tid = threadIdx.x;
    const int m0  = blockIdx.y * BM;
    const int n0  = blockIdx.x * BN;

    // loader mapping: thread -> (row, k4) inside 128x8 tile, one float4 each
    const int lrow = tid >> 1;
    const int lk   = (tid & 1) << 2;

    // compute mapping: 16x16 thread grid
    const int tm = tid >> 4;   // 0..15 -> rows tm*8 .. tm*8+7
    const int tn = tid & 15;   // 0..15 -> cols tn*4..+3 and 64+tn*4..+3

    const bool brow_ok = (n0 + lrow) < N_BANK;
    const float* Ap = A    + (size_t)(m0 + lrow) * K + lk;
    const float* Bp = Bank + (size_t)(brow_ok ? (n0 + lrow) : 0) * K + lk;

    unsigned long long acc[8][4];
    #pragma unroll
    for (int i = 0; i < 8; i++)
        #pragma unroll
        for (int j = 0; j < 4; j++) acc[i][j] = 0ULL;

    for (int k0 = 0; k0 < K; k0 += BKK) {
        float4 av = *reinterpret_cast<const float4*>(Ap + k0);
        float4 bv = make_float4(0.f, 0.f, 0.f, 0.f);
        if (brow_ok) bv = *reinterpret_cast<const float4*>(Bp + k0);

        As[lk + 0][lrow] = av.x; As[lk + 1][lrow] = av.y;
        As[lk + 2][lrow] = av.z; As[lk + 3][lrow] = av.w;
        Bs[lk + 0][lrow] = bv.x; Bs[lk + 1][lrow] = bv.y;
        Bs[lk + 2][lrow] = bv.z; Bs[lk + 3][lrow] = bv.w;
        __syncthreads();

        #pragma unroll
        for (int kk = 0; kk < BKK; kk++) {
            float4 a0 = *reinterpret_cast<const float4*>(&As[kk][tm * 8]);
            float4 a1 = *reinterpret_cast<const float4*>(&As[kk][tm * 8 + 4]);
            float4 b0 = *reinterpret_cast<const float4*>(&Bs[kk][tn * 4]);
            float4 b1 = *reinterpret_cast<const float4*>(&Bs[kk][64 + tn * 4]);

            unsigned long long bp0 = pk2(b0.x, b0.y);
            unsigned long long bp1 = pk2(b0.z, b0.w);
            unsigned long long bp2 = pk2(b1.x, b1.y);
            unsigned long long bp3 = pk2(b1.z, b1.w);
            float a[8] = {a0.x, a0.y, a0.z, a0.w, a1.x, a1.y, a1.z, a1.w};

            #pragma unroll
            for (int i = 0; i < 8; i++) {
                unsigned long long ad = pk2(a[i], a[i]);
                ffma2(acc[i][0], ad, bp0);
                ffma2(acc[i][1], ad, bp1);
                ffma2(acc[i][2], ad, bp2);
                ffma2(acc[i][3], ad, bp3);
            }
        }
        __syncthreads();
    }

    // epilogue: scale by bank inverse norm, store scores
    const int c0 = n0 + tn * 4;
    const int c1 = n0 + 64 + tn * 4;
    float w0[4], w1[4];
    #pragma unroll
    for (int j = 0; j < 4; j++) {
        w0[j] = (c0 + j < N_BANK) ? inv[c0 + j] : 0.f;
        w1[j] = (c1 + j < N_BANK) ? inv[c1 + j] : 0.f;
    }
    #pragma unroll
    for (int i = 0; i < 8; i++) {
        const int r = m0 + tm * 8 + i;
        float* cp = C + (size_t)r * N_BANK;
        float2 p0 = upk2(acc[i][0]); float2 p1 = upk2(acc[i][1]);
        float2 p2 = upk2(acc[i][2]); float2 p3 = upk2(acc[i][3]);
        float o0[4] = { p0.x * w0[0], p0.y * w0[1], p1.x * w0[2], p1.y * w0[3] };
        float o1[4] = { p2.x * w1[0], p2.y * w1[1], p3.x * w1[2], p3.y * w1[3] };
        if (c0 + 3 < N_BANK) {
            *reinterpret_cast<float4*>(cp + c0) = make_float4(o0[0], o0[1], o0[2], o0[3]);
        } else {
            #pragma unroll
            for (int j = 0; j < 4; j++) if (c0 + j < N_BANK) cp[c0 + j] = o0[j];
        }
        if (c1 + 3 < N_BANK) {
            *reinterpret_cast<float4*>(cp + c1) = make_float4(o1[0], o1[1], o1[2], o1[3]);
        } else {
            #pragma unroll
            for (int j = 0; j < 4; j++) if (c1 + j < N_BANK) cp[c1 + j] = o1[j];
        }
    }
}

// ---------------- 3) top-9 per row + metrics gather --------------------------
__device__ __forceinline__ void ins9(float s, int n, float v[KTOP], int id[KTOP]) {
    if (s <= v[KTOP - 1]) return;
    v[KTOP - 1]  = s;
    id[KTOP - 1] = n;
    #pragma unroll
    for (int q = KTOP - 1; q > 0; q--) {
        if (v[q] > v[q - 1]) {
            float tv = v[q]; v[q] = v[q - 1]; v[q - 1] = tv;
            int   ti = id[q]; id[q] = id[q - 1]; id[q - 1] = ti;
        }
    }
}

__global__ void topk_kernel(const float* __restrict__ metrics,
                            float* __restrict__ out,
                            int phase)   // 0: write g_partial; 1: finalize out
{
    __shared__ float sv[256 * KTOP];
    __shared__ int   si[256 * KTOP];
    __shared__ float sv2[32 * KTOP];
    __shared__ int   si2[32 * KTOP];

    const int b   = blockIdx.x;
    const int tid = threadIdx.x;
    const float* row = g_scores + (size_t)b * N_BANK;

    float v[KTOP]; int id[KTOP];
    #pragma unroll
    for (int i = 0; i < KTOP; i++) { v[i] = -3.402823466e38f; id[i] = 0; }

    for (int n = tid; n < N_BANK; n += 256) ins9(row[n], n, v, id);

    #pragma unroll
    for (int i = 0; i < KTOP; i++) { sv[tid * KTOP + i] = v[i]; si[tid * KTOP + i] = id[i]; }
    __syncthreads();

    if (tid < 32) {
        float mv[KTOP]; int mi[KTOP];
        #pragma unroll
        for (int i = 0; i < KTOP; i++) { mv[i] = -3.402823466e38f; mi[i] = 0; }
        for (int t = tid * 8; t < tid * 8 + 8; t++)
            for (int i = 0; i < KTOP; i++)
                ins9(sv[t * KTOP + i], si[t * KTOP + i], mv, mi);
        #pragma unroll
        for (int i = 0; i < KTOP; i++) { sv2[tid * KTOP + i] = mv[i]; si2[tid * KTOP + i] = mi[i]; }
    }
    __syncthreads();

    if (tid == 0) {
        float mv[KTOP]; int mi[KTOP];
        #pragma unroll
        for (int i = 0; i < KTOP; i++) { mv[i] = -3.402823466e38f; mi[i] = 0; }
        for (int t = 0; t < 32; t++)
            for (int i = 0; i < KTOP; i++)
                ins9(sv2[t * KTOP + i], si2[t * KTOP + i], mv, mi);
        float ssum = 0.f;
        #pragma unroll
        for (int i = 0; i < KTOP; i++) ssum += metrics[mi[i]];
        if (phase == 0) g_partial[b] = ssum;
        else            out[b] = (g_partial[b] + ssum) * (1.f / (2.f * KTOP));
    }
}

// ---------------- launch ------------------------------------------------------
extern "C" void kernel_launch(void* const* d_in, const int* in_sizes, int n_in,
                              void* d_out, int out_size) {
    // Identify inputs by element count (all distinct), robust to metadata order.
    const float* f_content    = nullptr;
    const float* f_distorsion = nullptr;
    const float* sem_bank     = nullptr;
    const float* dst_bank     = nullptr;
    const float* metrics      = nullptr;
    for (int i = 0; i < n_in; i++) {
        switch (in_sizes[i]) {
            case B_Q * DIM_S:            f_content    = (const float*)d_in[i]; break; // 1,048,576
            case B_Q * DIM_D:            f_distorsion = (const float*)d_in[i]; break; //   524,288
            case N_BANK * DIM_S:         sem_bank     = (const float*)d_in[i]; break; // 204,800,000
            case N_BANK * DIM_D:         dst_bank     = (const float*)d_in[i]; break; // 102,400,000
            case N_BANK:                 metrics      = (const float*)d_in[i]; break; //    50,000
            default: break; // scalar K (=9) ignored, compiled in
        }
    }
    float* out = (float*)d_out;

    // 1) bank inverse norms (both banks): 100000 warps
    {
        int warps = 2 * N_BANK;
        int blocks = (warps * 32 + 255) / 256;
        norm_kernel<<<blocks, 256>>>(sem_bank, dst_bank);
    }

    dim3 gemm_grid((N_BANK + BN - 1) / BN, B_Q / BM);  // (391, 2)

    // 2) semantic branch
    gemm_score_kernel<<<gemm_grid, 256>>>(f_content, sem_bank, /*which=*/0, DIM_S);
    topk_kernel<<<B_Q, 256>>>(metrics, out, /*phase=*/0);

    // 3) distorsion branch (reuses g_scores)
    gemm_score_kernel<<<gemm_grid, 256>>>(f_distorsion, dst_bank, /*which=*/1, DIM_D);
    topk_kernel<<<B_Q, 256>>>(metrics, out, /*phase=*/1);
}